// round 16
// baseline (speedup 1.0000x reference)
#include <cuda_runtime.h>
#include <cuda_fp16.h>
#include <cstdint>

#define BB 8
#define CC 64
#define NN 4096
#define KK 20
#define NCAND 48
#define NTARGET 24
#define OUTC 64
#define TM 128
#define TN 128
#define NUNITS 4224      /* 8 batches * 528 triangle blocks */
#define NCTA 296         /* 2 x 148 SMs */

// ===================== device scratch (allocation-free) =====================
__device__ __half g_hi[(size_t)BB * NN * CC];
__device__ float g_xp[(size_t)BB * NN * CC];
__device__ float g_sq[BB * NN];
__device__ unsigned short g_scor[(size_t)BB * NN * NN];  // flipped-fp16 scores, 256MB
__device__ int   g_idx[BB * NN * KK];
__device__ float g_u[(size_t)BB * NN * OUTC];
__device__ float g_v[(size_t)BB * NN * OUTC];
__device__ float g_mx[(size_t)BB * NN * OUTC];
__device__ float g_mn[(size_t)BB * NN * OUTC];
__device__ float g_sum[OUTC];
__device__ float g_sumsq[OUTC];
__device__ float g_s[OUTC];
__device__ float g_t[OUTC];

// ===================== helpers =====================
__device__ __forceinline__ void ldsm_x4(uint32_t addr, uint32_t* r) {
    asm volatile("ldmatrix.sync.aligned.m8n8.x4.shared.b16 {%0,%1,%2,%3}, [%4];"
                 : "=r"(r[0]), "=r"(r[1]), "=r"(r[2]), "=r"(r[3]) : "r"(addr));
}
__device__ __forceinline__ void mma16816h(uint32_t* d, const uint32_t* a, const uint32_t* b) {
    asm volatile("mma.sync.aligned.m16n8k16.row.col.f16.f16.f16.f16 "
                 "{%0,%1}, {%2,%3,%4,%5}, {%6,%7}, {%0,%1};"
                 : "+r"(d[0]), "+r"(d[1])
                 : "r"(a[0]), "r"(a[1]), "r"(a[2]), "r"(a[3]), "r"(b[0]), "r"(b[1]));
}
__device__ __forceinline__ uint32_t smem_u32(const void* p) {
    uint32_t a;
    asm("{ .reg .u64 t; cvta.to.shared.u64 t, %1; cvt.u32.u64 %0, t; }" : "=r"(a) : "l"(p));
    return a;
}
__device__ __forceinline__ uint32_t flip16x2u(uint32_t u) {
    return u ^ (0x80008000u | (((u >> 15) & 0x00010001u) * 0x7FFFu));
}
__device__ __forceinline__ uint32_t bcast_h2(float f) {
    __half h = __float2half_rn(f);
    __half2 h2 = __half2half2(h);
    return *reinterpret_cast<uint32_t*>(&h2);
}

// ===================== kernel A: sq norms + fp16 hi + fp32 point-major =====================
__global__ void __launch_bounds__(128) prep_kernel(const float* __restrict__ x) {
    int p = blockIdx.x * 128 + threadIdx.x;
    int b = p >> 12;
    int n = p & (NN - 1);
    const float* xb = x + (size_t)b * CC * NN + n;
    float s = 0.f;
#pragma unroll
    for (int g = 0; g < 8; g++) {
        uint4 h4;
        unsigned short* hp = (unsigned short*)&h4;
        float vf[8];
#pragma unroll
        for (int e = 0; e < 8; e++) {
            float v = xb[(size_t)(g * 8 + e) * NN];
            vf[e] = v;
            s = fmaf(v, v, s);
            hp[e] = __half_as_ushort(__float2half_rn(v));
        }
        *reinterpret_cast<uint4*>(g_hi + (size_t)p * CC + g * 8) = h4;
        *reinterpret_cast<float4*>(g_xp + (size_t)p * CC + g * 8) =
            make_float4(vf[0], vf[1], vf[2], vf[3]);
        *reinterpret_cast<float4*>(g_xp + (size_t)p * CC + g * 8 + 4) =
            make_float4(vf[4], vf[5], vf[6], vf[7]);
    }
    g_sq[p] = s;
    if (blockIdx.x == 0 && threadIdx.x < OUTC) {
        g_sum[threadIdx.x] = 0.f;
        g_sumsq[threadIdx.x] = 0.f;
    }
}

// ===================== kernel B1: triangular HMMA GEMM, balanced unit schedule =====================
#define SM_A     0          /* 128*144 = 18432 */
#define SM_B     18432      /* 2*18432 = 36864 */
#define SM_SQS   55296      /* 2*64*4 = 512 */
#define SM_DT    55808      /* 128*66*4 = 33792 transpose staging */
#define SM_TOTAL 89600

__global__ void __launch_bounds__(256, 2) knn_gemm_kernel() {
    extern __shared__ char sm[];
    const uint32_t smb = smem_u32(sm);
    const int tid = threadIdx.x;
    const int wid = tid >> 5;
    const int lane = tid & 31;

    const int u0 = (blockIdx.x * NUNITS) / NCTA;
    const int u1 = ((blockIdx.x + 1) * NUNITS) / NCTA;

    int b = u0 / 528;
    int t = u0 - b * 528;
    int rt = (int)((sqrtf(8.f * (float)t + 1.f) - 1.f) * 0.5f);
    while ((rt + 1) * (rt + 2) / 2 <= t) rt++;
    while (rt * (rt + 1) / 2 > t) rt--;
    int ct = t - rt * (rt + 1) / 2;

    uint32_t* sqs = (uint32_t*)(sm + SM_SQS);
    uint32_t* dt = (uint32_t*)(sm + SM_DT);

    const int wm = (wid & 3) * 32;
    const int wn = (wid >> 2) * 64;
    const int g = lane >> 2, t4 = lane & 3;
    const __half2 neg2 = __float2half2_rn(-2.f);

    {
        const __half* ha = g_hi + ((size_t)b * NN + rt * TM) * CC;
        for (int tt = 0; tt < 4; tt++) {
            int i = tid + tt * 256;
            int m = i >> 3, j = i & 7;
            *reinterpret_cast<uint4*>(sm + SM_A + m * 144 + j * 16) =
                *reinterpret_cast<const uint4*>(ha + (size_t)m * CC + j * 8);
        }
    }
    {
        const __half* hb = g_hi + ((size_t)b * NN + ct * TN) * CC;
        for (int tt = 0; tt < 4; tt++) {
            int i = tid + tt * 256;
            int n = i >> 3, j = i & 7;
            *reinterpret_cast<uint4*>(sm + SM_B + n * 144 + j * 16) =
                *reinterpret_cast<const uint4*>(hb + (size_t)n * CC + j * 8);
        }
        if (tid < 64) {
            float2 f = *reinterpret_cast<const float2*>(g_sq + b * NN + ct * TN + tid * 2);
            __half2 h = __floats2half2_rn(f.x, f.y);
            sqs[tid] = *reinterpret_cast<uint32_t*>(&h);
        }
    }
    uint32_t sqr[2][2];
#pragma unroll
    for (int mf = 0; mf < 2; mf++) {
        sqr[mf][0] = bcast_h2(g_sq[b * NN + rt * TM + wm + mf * 16 + g]);
        sqr[mf][1] = bcast_h2(g_sq[b * NN + rt * TM + wm + mf * 16 + g + 8]);
    }
    __syncthreads();

    uint4 pre[4];
    float2 sqnext = make_float2(0.f, 0.f);

    for (int u = u0; u < u1; u++) {
        const int buf = (u - u0) & 1;
        const uint32_t bsm = smb + SM_B + (uint32_t)buf * 18432u;
        const bool do_t = (ct != rt);

        int b2 = b, rt2 = rt, ct2 = ct + 1;
        const bool has_next = (u + 1 < u1);
        if (has_next && ct2 > rt2) { ct2 = 0; rt2++; if (rt2 >= 32) { rt2 = 0; b2++; } }

        if (has_next) {
            const __half* hb2 = g_hi + ((size_t)b2 * NN + ct2 * TN) * CC;
#pragma unroll
            for (int tt = 0; tt < 4; tt++) {
                int i = tid + tt * 256;
                int n = i >> 3, j = i & 7;
                pre[tt] = *reinterpret_cast<const uint4*>(hb2 + (size_t)n * CC + j * 8);
            }
            if (tid < 64) sqnext = *reinterpret_cast<const float2*>(g_sq + b2 * NN + ct2 * TN + tid * 2);
        }

        uint32_t acc[2][8][2];
#pragma unroll
        for (int mf = 0; mf < 2; mf++)
#pragma unroll
            for (int nt = 0; nt < 8; nt++) { acc[mf][nt][0] = 0u; acc[mf][nt][1] = 0u; }

#pragma unroll
        for (int ks = 0; ks < 4; ks++) {
            uint32_t a0[4], a1[4];
            uint32_t kb = (uint32_t)(ks * 16 + ((lane >> 4) << 3)) * 2u;
            uint32_t ar = (uint32_t)(wm + (lane & 15)) * 144u;
            ldsm_x4(smb + SM_A + ar + kb, a0);
            ldsm_x4(smb + SM_A + ar + 16u * 144u + kb, a1);
#pragma unroll
            for (int ntp = 0; ntp < 4; ntp++) {
                uint32_t bh[4];
                uint32_t bn = (uint32_t)(wn + ntp * 16 + ((lane >> 4) << 3) + (lane & 7));
                uint32_t bk = (uint32_t)(ks * 16 + (((lane >> 3) & 1) << 3));
                ldsm_x4(bsm + bn * 144u + bk * 2u, bh);
                mma16816h(acc[0][2 * ntp],     a0, bh);
                mma16816h(acc[0][2 * ntp + 1], a0, bh + 2);
                mma16816h(acc[1][2 * ntp],     a1, bh);
                mma16816h(acc[1][2 * ntp + 1], a1, bh + 2);
            }
        }

        if (has_next) {
            char* dstb = sm + SM_B + (buf ^ 1) * 18432;
#pragma unroll
            for (int tt = 0; tt < 4; tt++) {
                int i = tid + tt * 256;
                int n = i >> 3, j = i & 7;
                *reinterpret_cast<uint4*>(dstb + n * 144 + j * 16) = pre[tt];
            }
            if (tid < 64) {
                __half2 h = __floats2half2_rn(sqnext.x, sqnext.y);
                sqs[(buf ^ 1) * 64 + tid] = *reinterpret_cast<uint32_t*>(&h);
            }
        }

        {
            const uint32_t* sqb = sqs + buf * 64 + (wn >> 1);
#pragma unroll
            for (int mf = 0; mf < 2; mf++) {
                unsigned short* dout = g_scor +
                    ((size_t)(b * NN) + rt * TM + wm + mf * 16 + g) * NN + ct * TN + wn;
#pragma unroll
                for (int nt = 0; nt < 8; nt++) {
                    int c0 = nt * 8 + t4 * 2;
                    uint32_t squ = sqb[nt * 4 + t4];
                    __half2 sqh = *reinterpret_cast<__half2*>(&squ);
                    __half2 s0 = __hfma2(*reinterpret_cast<__half2*>(&acc[mf][nt][0]), neg2, sqh);
                    __half2 s1 = __hfma2(*reinterpret_cast<__half2*>(&acc[mf][nt][1]), neg2, sqh);
                    *reinterpret_cast<uint32_t*>(dout + c0) =
                        flip16x2u(*reinterpret_cast<uint32_t*>(&s0));
                    *reinterpret_cast<uint32_t*>(dout + (size_t)8 * NN + c0) =
                        flip16x2u(*reinterpret_cast<uint32_t*>(&s1));

                    __half2 sqr0 = *reinterpret_cast<__half2*>(&sqr[mf][0]);
                    __half2 sqr1 = *reinterpret_cast<__half2*>(&sqr[mf][1]);
                    __half2 t0 = __hfma2(*reinterpret_cast<__half2*>(&acc[mf][nt][0]), neg2, sqr0);
                    __half2 t1 = __hfma2(*reinterpret_cast<__half2*>(&acc[mf][nt][1]), neg2, sqr1);
                    uint32_t st0 = flip16x2u(*reinterpret_cast<uint32_t*>(&t0));
                    uint32_t st1 = flip16x2u(*reinterpret_cast<uint32_t*>(&t1));
                    uint32_t q0 = __shfl_down_sync(0xffffffffu, st0, 4);
                    uint32_t q1 = __shfl_down_sync(0xffffffffu, st1, 4);
                    if (do_t && !(g & 1)) {
                        int rr = (wm >> 1) + mf * 8 + (g >> 1);
                        int cc = wn + c0;
                        dt[cc * 66 + rr]           = __byte_perm(st0, q0, 0x5410);
                        dt[(cc + 1) * 66 + rr]     = __byte_perm(st0, q0, 0x7632);
                        dt[cc * 66 + rr + 4]       = __byte_perm(st1, q1, 0x5410);
                        dt[(cc + 1) * 66 + rr + 4] = __byte_perm(st1, q1, 0x7632);
                    }
                }
            }
        }
        __syncthreads();

        if (do_t) {
            uint32_t* sc32 = reinterpret_cast<uint32_t*>(g_scor);
            size_t baserow = (size_t)(b * NN + ct * TN);
#pragma unroll 8
            for (int tt = 0; tt < 32; tt++) {
                int i = tid + tt * 256;
                int c = i >> 6, k = i & 63;
                sc32[(baserow + c) * (NN / 2) + rt * 64 + k] = dt[c * 66 + k];
            }
        }

        const bool across = has_next && (rt2 != rt || b2 != b);
        if (across) {
            const __half* ha = g_hi + ((size_t)b2 * NN + rt2 * TM) * CC;
            for (int tt = 0; tt < 4; tt++) {
                int i = tid + tt * 256;
                int m = i >> 3, j = i & 7;
                *reinterpret_cast<uint4*>(sm + SM_A + m * 144 + j * 16) =
                    *reinterpret_cast<const uint4*>(ha + (size_t)m * CC + j * 8);
            }
#pragma unroll
            for (int mf = 0; mf < 2; mf++) {
                sqr[mf][0] = bcast_h2(g_sq[b2 * NN + rt2 * TM + wm + mf * 16 + g]);
                sqr[mf][1] = bcast_h2(g_sq[b2 * NN + rt2 * TM + wm + mf * 16 + g + 8]);
            }
        }
        __syncthreads();

        b = b2; rt = rt2; ct = ct2;
    }
}

// ===================== kernel B2: select+rerank, 2 rows per 256-thread block =====================
__global__ void __launch_bounds__(256) select_rerank_kernel() {
    __shared__ uint32_t wsum[2][8];
    __shared__ uint32_t fdone[2][2];
    __shared__ uint32_t counter[2];
    __shared__ int   cidx[2][NCAND];
    __shared__ float csc[2][NCAND];

    const int tid = threadIdx.x;
    const int half = tid >> 7;
    const int htid = tid & 127;
    const int wrp = tid >> 5;        // 0..7
    const int lane = tid & 31;
    const int p = blockIdx.x * 2 + half;
    const uint4* r4 = reinterpret_cast<const uint4*>(g_scor + (size_t)p * NN);

    uint4 v[4];
#pragma unroll
    for (int j = 0; j < 4; j++) v[j] = r4[j * 128 + htid];

    if (tid < 2) counter[tid] = 0;

    uint32_t lo = 0, hi = 0x10000u, cut = 0x10000u;
    bool found = false;

#pragma unroll 1
    for (int it = 0; it < 18; it++) {
        if (lane == 0 && (wrp & 3) == 0) fdone[it & 1][half] = found ? 1u : 0u;
        uint32_t mid = found ? cut : ((lo + hi) >> 1);
        uint32_t c = 0;
#pragma unroll
        for (int j = 0; j < 4; j++) {
            const uint32_t* u4 = (const uint32_t*)&v[j];
#pragma unroll
            for (int e = 0; e < 4; e++) {
                uint32_t u = u4[e];
                c += ((u & 0xFFFFu) < mid) + ((u >> 16) < mid);
            }
        }
        c = __reduce_add_sync(0xffffffffu, c);
        if (lane == 0) wsum[it & 1][wrp] = c;
        __syncthreads();
        if (fdone[it & 1][0] && fdone[it & 1][1]) break;
        if (!found) {
            uint32_t tot = wsum[it & 1][half * 4 + 0] + wsum[it & 1][half * 4 + 1] +
                           wsum[it & 1][half * 4 + 2] + wsum[it & 1][half * 4 + 3];
            if (tot >= NTARGET && tot <= NCAND) { cut = mid; found = true; }
            else {
                if (tot >= NTARGET) hi = mid; else lo = mid;
                if (hi - lo <= 1) { cut = hi; found = true; }
            }
        }
    }
    __syncthreads();

    // compaction into smem
#pragma unroll
    for (int j = 0; j < 4; j++) {
        const uint32_t* u4 = (const uint32_t*)&v[j];
#pragma unroll
        for (int e = 0; e < 4; e++) {
            uint32_t u = u4[e];
            int i32 = 4 * (j * 128 + htid) + e;
            if ((u & 0xFFFFu) < cut) {
                uint32_t slot = atomicAdd(&counter[half], 1);
                if (slot < NCAND) cidx[half][slot] = 2 * i32;
            }
            if ((u >> 16) < cut) {
                uint32_t slot = atomicAdd(&counter[half], 1);
                if (slot < NCAND) cidx[half][slot] = 2 * i32 + 1;
            }
        }
    }
    __syncthreads();
    int cnt = counter[half] < NCAND ? (int)counter[half] : NCAND;
    int bbase = (p >> 12) << 12;

    // exact fp32 rescoring: one thread per candidate (per half)
    if (htid < NCAND) {
        if (htid < cnt) {
            int c = cidx[half][htid];
            const float* xr = g_xp + (size_t)p * CC;
            const float* xc = g_xp + (size_t)(bbase + c) * CC;
            float d = 0.f;
#pragma unroll
            for (int i = 0; i < 16; i++) {
                float4 a = *reinterpret_cast<const float4*>(xr + i * 4);
                float4 bq = *reinterpret_cast<const float4*>(xc + i * 4);
                d = fmaf(a.x, bq.x, d);
                d = fmaf(a.y, bq.y, d);
                d = fmaf(a.z, bq.z, d);
                d = fmaf(a.w, bq.w, d);
            }
            csc[half][htid] = fmaf(-2.f, d, g_sq[bbase + c]);
        } else {
            csc[half][htid] = 3.0e38f;
            cidx[half][htid] = 0x7fffffff;
        }
    }
    __syncthreads();

    // rank counting -> top-20 (per half)
    if (htid < NCAND) {
        float s = csc[half][htid];
        int   ii = cidx[half][htid];
        int r = 0;
#pragma unroll
        for (int j = 0; j < NCAND; j++) {
            float sj = csc[half][j];
            int ij = cidx[half][j];
            r += (sj < s) || (sj == s && ij < ii);
        }
        if (r < KK) g_idx[(size_t)p * KK + r] = ii;
    }
}

// ===================== kernel C: u = W1 @ x, v = (W2-W1) @ x (8 outputs/thread) =====================
__global__ void __launch_bounds__(128) gemm_uv_kernel(const float* __restrict__ x,
                                                      const float* __restrict__ W) {
    int b = blockIdx.z, og = blockIdx.y;
    int n = blockIdx.x * 128 + threadIdx.x;

    __shared__ float W1s[8][64];
    __shared__ float Wds[8][64];
    for (int i = threadIdx.x; i < 8 * 64; i += 128) {
        int oo = i >> 6, c = i & 63;
        int o = og * 8 + oo;
        float w1 = W[o * 2 * CC + c];
        float w2 = W[o * 2 * CC + CC + c];
        W1s[oo][c] = w1;
        Wds[oo][c] = w2 - w1;
    }
    __syncthreads();

    float ua[8], va[8];
#pragma unroll
    for (int oo = 0; oo < 8; oo++) { ua[oo] = 0.f; va[oo] = 0.f; }

    const float* xb = x + (size_t)b * CC * NN + n;
#pragma unroll
    for (int ch = 0; ch < CC; ch++) {
        float xv = xb[(size_t)ch * NN];
#pragma unroll
        for (int oo = 0; oo < 8; oo++) {
            ua[oo] = fmaf(W1s[oo][ch], xv, ua[oo]);
            va[oo] = fmaf(Wds[oo][ch], xv, va[oo]);
        }
    }

    float* up = g_u + ((size_t)b * NN + n) * OUTC + og * 8;
    float* vp = g_v + ((size_t)b * NN + n) * OUTC + og * 8;
#pragma unroll
    for (int oo = 0; oo < 8; oo += 4) {
        *reinterpret_cast<float4*>(up + oo) = make_float4(ua[oo], ua[oo + 1], ua[oo + 2], ua[oo + 3]);
        *reinterpret_cast<float4*>(vp + oo) = make_float4(va[oo], va[oo + 1], va[oo + 2], va[oo + 3]);
    }
}

// ===================== kernel D: edges =====================
__global__ void __launch_bounds__(256) edge_kernel() {
    __shared__ float ssum[OUTC];
    __shared__ float ssq[OUTC];
    int tid = threadIdx.x, lane = tid & 31, wrp = tid >> 5;
    if (tid < OUTC) { ssum[tid] = 0.f; ssq[tid] = 0.f; }
    __syncthreads();

    int p0 = blockIdx.x * 64;
    float lsum0 = 0.f, lsq0 = 0.f, lsum1 = 0.f, lsq1 = 0.f;

    for (int i = 0; i < 8; i++) {
        int p = p0 + wrp * 8 + i;
        const float* vp = g_v + (size_t)p * OUTC;
        float v0 = vp[lane], v1 = vp[lane + 32];
        int idxv = 0;
        if (lane < KK) idxv = g_idx[(size_t)p * KK + lane];
        int bbase = (p >> 12) << 12;

        float mx0 = -3.0e38f, mn0 = 3.0e38f, mx1 = -3.0e38f, mn1 = 3.0e38f;
#pragma unroll
        for (int k = 0; k < KK; k++) {
            int j = __shfl_sync(0xffffffffu, idxv, k);
            const float* uj = g_u + (size_t)(bbase + j) * OUTC;
            float z0 = uj[lane] + v0;
            float z1 = uj[lane + 32] + v1;
            mx0 = fmaxf(mx0, z0); mn0 = fminf(mn0, z0);
            mx1 = fmaxf(mx1, z1); mn1 = fminf(mn1, z1);
            lsum0 += z0; lsq0 = fmaf(z0, z0, lsq0);
            lsum1 += z1; lsq1 = fmaf(z1, z1, lsq1);
        }
        float* mxp = g_mx + (size_t)p * OUTC;
        float* mnp = g_mn + (size_t)p * OUTC;
        mxp[lane] = mx0; mxp[lane + 32] = mx1;
        mnp[lane] = mn0; mnp[lane + 32] = mn1;
    }

    atomicAdd(&ssum[lane], lsum0);
    atomicAdd(&ssum[lane + 32], lsum1);
    atomicAdd(&ssq[lane], lsq0);
    atomicAdd(&ssq[lane + 32], lsq1);
    __syncthreads();
    if (tid < OUTC) {
        atomicAdd(&g_sum[tid], ssum[tid]);
        atomicAdd(&g_sumsq[tid], ssq[tid]);
    }
}

// ===================== kernel E0: finalize BN affine =====================
__global__ void stats_kernel(const float* __restrict__ gamma, const float* __restrict__ beta) {
    int o = threadIdx.x;
    const float cnt = (float)((size_t)BB * NN * KK);
    float mean = g_sum[o] / cnt;
    float var = g_sumsq[o] / cnt - mean * mean;
    float s = gamma[o] * rsqrtf(var + 1e-5f);
    g_s[o] = s;
    g_t[o] = fmaf(-mean, s, beta[o]);
}

// ===================== kernel E: BN + LeakyReLU + transpose =====================
__global__ void __launch_bounds__(256) out_kernel(float* __restrict__ out) {
    __shared__ float tile[64][65];
    __shared__ float ss[OUTC], tt[OUTC];
    int tid = threadIdx.x;
    if (tid < OUTC) { ss[tid] = g_s[tid]; tt[tid] = g_t[tid]; }
    __syncthreads();

    int p0 = blockIdx.x * 64;
    int b = p0 >> 12;
    int n0 = p0 & (NN - 1);

#pragma unroll
    for (int j = 0; j < 16; j++) {
        int i = tid + j * 256;
        int nn = i >> 6, o = i & 63;
        size_t base = (size_t)(p0 + nn) * OUTC + o;
        float s = ss[o];
        float z = (s >= 0.f) ? g_mx[base] : g_mn[base];
        float y = fmaf(s, z, tt[o]);
        y = (y >= 0.f) ? y : 0.2f * y;
        tile[o][nn] = y;
    }
    __syncthreads();
#pragma unroll
    for (int j = 0; j < 16; j++) {
        int i = tid + j * 256;
        int o = i >> 6, nn = i & 63;
        out[((size_t)(b * OUTC + o)) * NN + n0 + nn] = tile[o][nn];
    }
}

// ===================== launch =====================
extern "C" void kernel_launch(void* const* d_in, const int* in_sizes, int n_in,
                              void* d_out, int out_size) {
    const float* x     = (const float*)d_in[0];
    const float* W     = (const float*)d_in[1];
    const float* gamma = (const float*)d_in[2];
    const float* beta  = (const float*)d_in[3];
    float* out = (float*)d_out;

    // created once on the (uncaptured) correctness call; reused in capture
    static cudaStream_t s2 = nullptr;
    static cudaEvent_t evA = nullptr, evB = nullptr;
    if (s2 == nullptr) {
        cudaStreamCreateWithFlags(&s2, cudaStreamNonBlocking);
        cudaEventCreateWithFlags(&evA, cudaEventDisableTiming);
        cudaEventCreateWithFlags(&evB, cudaEventDisableTiming);
        cudaFuncSetAttribute(knn_gemm_kernel, cudaFuncAttributeMaxDynamicSharedMemorySize, SM_TOTAL);
    }

    // fork: uv depends only on input x — run it concurrently with prep/knn/select
    cudaEventRecord(evA, 0);
    cudaStreamWaitEvent(s2, evA, 0);
    gemm_uv_kernel<<<dim3(NN / 128, 8, BB), 128, 0, s2>>>(x, W);
    cudaEventRecord(evB, s2);

    prep_kernel<<<(BB * NN) / 128, 128>>>(x);
    knn_gemm_kernel<<<NCTA, 256, SM_TOTAL>>>();
    select_rerank_kernel<<<(BB * NN) / 2, 256>>>();

    cudaStreamWaitEvent(0, evB, 0);   // join before edge consumes g_u/g_v
    edge_kernel<<<(BB * NN) / 64, 256>>>();
    stats_kernel<<<1, OUTC>>>(gamma, beta);
    out_kernel<<<(BB * NN) / 64, 256>>>(out);
}

// round 17
// speedup vs baseline: 1.1141x; 1.1141x over previous
#include <cuda_runtime.h>
#include <cuda_fp16.h>
#include <cstdint>

#define BB 8
#define CC 64
#define NN 4096
#define KK 20
#define NCAND 48
#define NTARGET 24
#define OUTC 64
#define TM 128
#define TN 128
#define NUNITS 4224      /* 8 batches * 528 triangle blocks */
#define NCTA 296         /* 2 x 148 SMs */

// ===================== device scratch (allocation-free) =====================
__device__ __half g_hi[(size_t)BB * NN * CC];
__device__ float g_xp[(size_t)BB * NN * CC];
__device__ float g_sq[BB * NN];
__device__ unsigned short g_scor[(size_t)BB * NN * NN];  // flipped-fp16 scores, 256MB
__device__ int   g_idx[BB * NN * KK];
__device__ float g_u[(size_t)BB * NN * OUTC];
__device__ float g_v[(size_t)BB * NN * OUTC];
__device__ float g_mx[(size_t)BB * NN * OUTC];
__device__ float g_mn[(size_t)BB * NN * OUTC];
__device__ float g_sum[OUTC];
__device__ float g_sumsq[OUTC];
__device__ float g_s[OUTC];
__device__ float g_t[OUTC];

// ===================== helpers =====================
__device__ __forceinline__ void ldsm_x4(uint32_t addr, uint32_t* r) {
    asm volatile("ldmatrix.sync.aligned.m8n8.x4.shared.b16 {%0,%1,%2,%3}, [%4];"
                 : "=r"(r[0]), "=r"(r[1]), "=r"(r[2]), "=r"(r[3]) : "r"(addr));
}
__device__ __forceinline__ void mma16816h(uint32_t* d, const uint32_t* a, const uint32_t* b) {
    asm volatile("mma.sync.aligned.m16n8k16.row.col.f16.f16.f16.f16 "
                 "{%0,%1}, {%2,%3,%4,%5}, {%6,%7}, {%0,%1};"
                 : "+r"(d[0]), "+r"(d[1])
                 : "r"(a[0]), "r"(a[1]), "r"(a[2]), "r"(a[3]), "r"(b[0]), "r"(b[1]));
}
__device__ __forceinline__ uint32_t smem_u32(const void* p) {
    uint32_t a;
    asm("{ .reg .u64 t; cvta.to.shared.u64 t, %1; cvt.u32.u64 %0, t; }" : "=r"(a) : "l"(p));
    return a;
}
__device__ __forceinline__ uint32_t flip16x2u(uint32_t u) {
    return u ^ (0x80008000u | (((u >> 15) & 0x00010001u) * 0x7FFFu));
}
__device__ __forceinline__ uint32_t bcast_h2(float f) {
    __half h = __float2half_rn(f);
    __half2 h2 = __half2half2(h);
    return *reinterpret_cast<uint32_t*>(&h2);
}

// ===================== kernel A: sq norms + fp16 hi + fp32 point-major =====================
__global__ void __launch_bounds__(128) prep_kernel(const float* __restrict__ x) {
    int p = blockIdx.x * 128 + threadIdx.x;
    int b = p >> 12;
    int n = p & (NN - 1);
    const float* xb = x + (size_t)b * CC * NN + n;
    float s = 0.f;
#pragma unroll
    for (int g = 0; g < 8; g++) {
        uint4 h4;
        unsigned short* hp = (unsigned short*)&h4;
        float vf[8];
#pragma unroll
        for (int e = 0; e < 8; e++) {
            float v = xb[(size_t)(g * 8 + e) * NN];
            vf[e] = v;
            s = fmaf(v, v, s);
            hp[e] = __half_as_ushort(__float2half_rn(v));
        }
        *reinterpret_cast<uint4*>(g_hi + (size_t)p * CC + g * 8) = h4;
        *reinterpret_cast<float4*>(g_xp + (size_t)p * CC + g * 8) =
            make_float4(vf[0], vf[1], vf[2], vf[3]);
        *reinterpret_cast<float4*>(g_xp + (size_t)p * CC + g * 8 + 4) =
            make_float4(vf[4], vf[5], vf[6], vf[7]);
    }
    g_sq[p] = s;
    if (blockIdx.x == 0 && threadIdx.x < OUTC) {
        g_sum[threadIdx.x] = 0.f;
        g_sumsq[threadIdx.x] = 0.f;
    }
}

// ===================== kernel B1: triangular HMMA GEMM, balanced unit schedule =====================
#define SM_A     0          /* 128*144 = 18432 */
#define SM_B     18432      /* 2*18432 = 36864 */
#define SM_SQS   55296      /* 2*64*4 = 512 */
#define SM_DT    55808      /* 128*66*4 = 33792 transpose staging */
#define SM_TOTAL 89600

__global__ void __launch_bounds__(256, 2) knn_gemm_kernel() {
    extern __shared__ char sm[];
    const uint32_t smb = smem_u32(sm);
    const int tid = threadIdx.x;
    const int wid = tid >> 5;
    const int lane = tid & 31;

    const int u0 = (blockIdx.x * NUNITS) / NCTA;
    const int u1 = ((blockIdx.x + 1) * NUNITS) / NCTA;

    int b = u0 / 528;
    int t = u0 - b * 528;
    int rt = (int)((sqrtf(8.f * (float)t + 1.f) - 1.f) * 0.5f);
    while ((rt + 1) * (rt + 2) / 2 <= t) rt++;
    while (rt * (rt + 1) / 2 > t) rt--;
    int ct = t - rt * (rt + 1) / 2;

    uint32_t* sqs = (uint32_t*)(sm + SM_SQS);
    uint32_t* dt = (uint32_t*)(sm + SM_DT);

    const int wm = (wid & 3) * 32;
    const int wn = (wid >> 2) * 64;
    const int g = lane >> 2, t4 = lane & 3;
    const __half2 neg2 = __float2half2_rn(-2.f);

    {
        const __half* ha = g_hi + ((size_t)b * NN + rt * TM) * CC;
        for (int tt = 0; tt < 4; tt++) {
            int i = tid + tt * 256;
            int m = i >> 3, j = i & 7;
            *reinterpret_cast<uint4*>(sm + SM_A + m * 144 + j * 16) =
                *reinterpret_cast<const uint4*>(ha + (size_t)m * CC + j * 8);
        }
    }
    {
        const __half* hb = g_hi + ((size_t)b * NN + ct * TN) * CC;
        for (int tt = 0; tt < 4; tt++) {
            int i = tid + tt * 256;
            int n = i >> 3, j = i & 7;
            *reinterpret_cast<uint4*>(sm + SM_B + n * 144 + j * 16) =
                *reinterpret_cast<const uint4*>(hb + (size_t)n * CC + j * 8);
        }
        if (tid < 64) {
            float2 f = *reinterpret_cast<const float2*>(g_sq + b * NN + ct * TN + tid * 2);
            __half2 h = __floats2half2_rn(f.x, f.y);
            sqs[tid] = *reinterpret_cast<uint32_t*>(&h);
        }
    }
    uint32_t sqr[2][2];
#pragma unroll
    for (int mf = 0; mf < 2; mf++) {
        sqr[mf][0] = bcast_h2(g_sq[b * NN + rt * TM + wm + mf * 16 + g]);
        sqr[mf][1] = bcast_h2(g_sq[b * NN + rt * TM + wm + mf * 16 + g + 8]);
    }
    __syncthreads();

    uint4 pre[4];
    float2 sqnext = make_float2(0.f, 0.f);

    for (int u = u0; u < u1; u++) {
        const int buf = (u - u0) & 1;
        const uint32_t bsm = smb + SM_B + (uint32_t)buf * 18432u;
        const bool do_t = (ct != rt);

        int b2 = b, rt2 = rt, ct2 = ct + 1;
        const bool has_next = (u + 1 < u1);
        if (has_next && ct2 > rt2) { ct2 = 0; rt2++; if (rt2 >= 32) { rt2 = 0; b2++; } }

        if (has_next) {
            const __half* hb2 = g_hi + ((size_t)b2 * NN + ct2 * TN) * CC;
#pragma unroll
            for (int tt = 0; tt < 4; tt++) {
                int i = tid + tt * 256;
                int n = i >> 3, j = i & 7;
                pre[tt] = *reinterpret_cast<const uint4*>(hb2 + (size_t)n * CC + j * 8);
            }
            if (tid < 64) sqnext = *reinterpret_cast<const float2*>(g_sq + b2 * NN + ct2 * TN + tid * 2);
        }

        uint32_t acc[2][8][2];
#pragma unroll
        for (int mf = 0; mf < 2; mf++)
#pragma unroll
            for (int nt = 0; nt < 8; nt++) { acc[mf][nt][0] = 0u; acc[mf][nt][1] = 0u; }

#pragma unroll
        for (int ks = 0; ks < 4; ks++) {
            uint32_t a0[4], a1[4];
            uint32_t kb = (uint32_t)(ks * 16 + ((lane >> 4) << 3)) * 2u;
            uint32_t ar = (uint32_t)(wm + (lane & 15)) * 144u;
            ldsm_x4(smb + SM_A + ar + kb, a0);
            ldsm_x4(smb + SM_A + ar + 16u * 144u + kb, a1);
#pragma unroll
            for (int ntp = 0; ntp < 4; ntp++) {
                uint32_t bh[4];
                uint32_t bn = (uint32_t)(wn + ntp * 16 + ((lane >> 4) << 3) + (lane & 7));
                uint32_t bk = (uint32_t)(ks * 16 + (((lane >> 3) & 1) << 3));
                ldsm_x4(bsm + bn * 144u + bk * 2u, bh);
                mma16816h(acc[0][2 * ntp],     a0, bh);
                mma16816h(acc[0][2 * ntp + 1], a0, bh + 2);
                mma16816h(acc[1][2 * ntp],     a1, bh);
                mma16816h(acc[1][2 * ntp + 1], a1, bh + 2);
            }
        }

        if (has_next) {
            char* dstb = sm + SM_B + (buf ^ 1) * 18432;
#pragma unroll
            for (int tt = 0; tt < 4; tt++) {
                int i = tid + tt * 256;
                int n = i >> 3, j = i & 7;
                *reinterpret_cast<uint4*>(dstb + n * 144 + j * 16) = pre[tt];
            }
            if (tid < 64) {
                __half2 h = __floats2half2_rn(sqnext.x, sqnext.y);
                sqs[(buf ^ 1) * 64 + tid] = *reinterpret_cast<uint32_t*>(&h);
            }
        }

        {
            const uint32_t* sqb = sqs + buf * 64 + (wn >> 1);
#pragma unroll
            for (int mf = 0; mf < 2; mf++) {
                unsigned short* dout = g_scor +
                    ((size_t)(b * NN) + rt * TM + wm + mf * 16 + g) * NN + ct * TN + wn;
#pragma unroll
                for (int nt = 0; nt < 8; nt++) {
                    int c0 = nt * 8 + t4 * 2;
                    uint32_t squ = sqb[nt * 4 + t4];
                    __half2 sqh = *reinterpret_cast<__half2*>(&squ);
                    __half2 s0 = __hfma2(*reinterpret_cast<__half2*>(&acc[mf][nt][0]), neg2, sqh);
                    __half2 s1 = __hfma2(*reinterpret_cast<__half2*>(&acc[mf][nt][1]), neg2, sqh);
                    *reinterpret_cast<uint32_t*>(dout + c0) =
                        flip16x2u(*reinterpret_cast<uint32_t*>(&s0));
                    *reinterpret_cast<uint32_t*>(dout + (size_t)8 * NN + c0) =
                        flip16x2u(*reinterpret_cast<uint32_t*>(&s1));

                    __half2 sqr0 = *reinterpret_cast<__half2*>(&sqr[mf][0]);
                    __half2 sqr1 = *reinterpret_cast<__half2*>(&sqr[mf][1]);
                    __half2 t0 = __hfma2(*reinterpret_cast<__half2*>(&acc[mf][nt][0]), neg2, sqr0);
                    __half2 t1 = __hfma2(*reinterpret_cast<__half2*>(&acc[mf][nt][1]), neg2, sqr1);
                    uint32_t st0 = flip16x2u(*reinterpret_cast<uint32_t*>(&t0));
                    uint32_t st1 = flip16x2u(*reinterpret_cast<uint32_t*>(&t1));
                    uint32_t q0 = __shfl_down_sync(0xffffffffu, st0, 4);
                    uint32_t q1 = __shfl_down_sync(0xffffffffu, st1, 4);
                    if (do_t && !(g & 1)) {
                        int rr = (wm >> 1) + mf * 8 + (g >> 1);
                        int cc = wn + c0;
                        dt[cc * 66 + rr]           = __byte_perm(st0, q0, 0x5410);
                        dt[(cc + 1) * 66 + rr]     = __byte_perm(st0, q0, 0x7632);
                        dt[cc * 66 + rr + 4]       = __byte_perm(st1, q1, 0x5410);
                        dt[(cc + 1) * 66 + rr + 4] = __byte_perm(st1, q1, 0x7632);
                    }
                }
            }
        }
        __syncthreads();

        if (do_t) {
            uint32_t* sc32 = reinterpret_cast<uint32_t*>(g_scor);
            size_t baserow = (size_t)(b * NN + ct * TN);
#pragma unroll 8
            for (int tt = 0; tt < 32; tt++) {
                int i = tid + tt * 256;
                int c = i >> 6, k = i & 63;
                sc32[(baserow + c) * (NN / 2) + rt * 64 + k] = dt[c * 66 + k];
            }
        }

        const bool across = has_next && (rt2 != rt || b2 != b);
        if (across) {
            const __half* ha = g_hi + ((size_t)b2 * NN + rt2 * TM) * CC;
            for (int tt = 0; tt < 4; tt++) {
                int i = tid + tt * 256;
                int m = i >> 3, j = i & 7;
                *reinterpret_cast<uint4*>(sm + SM_A + m * 144 + j * 16) =
                    *reinterpret_cast<const uint4*>(ha + (size_t)m * CC + j * 8);
            }
#pragma unroll
            for (int mf = 0; mf < 2; mf++) {
                sqr[mf][0] = bcast_h2(g_sq[b2 * NN + rt2 * TM + wm + mf * 16 + g]);
                sqr[mf][1] = bcast_h2(g_sq[b2 * NN + rt2 * TM + wm + mf * 16 + g + 8]);
            }
        }
        __syncthreads();

        b = b2; rt = rt2; ct = ct2;
    }
}

// ===================== kernel B2: select (SIMD-count binary search) + exact rerank =====================
__global__ void __launch_bounds__(128) select_rerank_kernel() {
    __shared__ uint32_t wsum[2][4];
    __shared__ uint32_t counter;
    __shared__ int   cidx[NCAND];
    __shared__ float csc[NCAND];

    const int tid = threadIdx.x;
    const int wrp = tid >> 5;
    const int lane = tid & 31;
    const int p = blockIdx.x;
    const uint4* r4 = reinterpret_cast<const uint4*>(g_scor + (size_t)p * NN);

    // load 32 u16 scores per thread (coalesced uint4)
    uint4 v[4];
#pragma unroll
    for (int j = 0; j < 4; j++) v[j] = r4[j * 128 + tid];

    uint32_t lo = 0, hi = 0x10000u, cut = 0x10000u;

#pragma unroll 1
    for (int it = 0; it < 17; it++) {
        uint32_t mid = (lo + hi) >> 1;           // mid <= 0xFFFF always
        uint32_t mid2 = mid * 0x10001u;          // packed halfword pair
        uint32_t c2 = 0;
#pragma unroll
        for (int j = 0; j < 4; j++) {
            const uint32_t* u4 = (const uint32_t*)&v[j];
            c2 += __vsetltu2(u4[0], mid2);
            c2 += __vsetltu2(u4[1], mid2);
            c2 += __vsetltu2(u4[2], mid2);
            c2 += __vsetltu2(u4[3], mid2);
        }
        uint32_t c = (c2 & 0xFFFFu) + (c2 >> 16);
        c = __reduce_add_sync(0xffffffffu, c);
        if (lane == 0) wsum[it & 1][wrp] = c;
        __syncthreads();
        uint32_t tot = wsum[it & 1][0] + wsum[it & 1][1] + wsum[it & 1][2] + wsum[it & 1][3];
        if (tot >= NTARGET && tot <= NCAND) { cut = mid; break; }
        if (tot >= NTARGET) hi = mid; else lo = mid;
        if (hi - lo <= 1) { cut = hi; break; }
    }

    if (tid == 0) counter = 0;
    __syncthreads();

    // compaction into smem
#pragma unroll
    for (int j = 0; j < 4; j++) {
        const uint32_t* u4 = (const uint32_t*)&v[j];
#pragma unroll
        for (int e = 0; e < 4; e++) {
            uint32_t u = u4[e];
            int i32 = 4 * (j * 128 + tid) + e;
            if ((u & 0xFFFFu) < cut) {
                uint32_t slot = atomicAdd(&counter, 1);
                if (slot < NCAND) cidx[slot] = 2 * i32;
            }
            if ((u >> 16) < cut) {
                uint32_t slot = atomicAdd(&counter, 1);
                if (slot < NCAND) cidx[slot] = 2 * i32 + 1;
            }
        }
    }
    __syncthreads();
    int cnt = counter < NCAND ? (int)counter : NCAND;
    int bbase = (p >> 12) << 12;

    // exact fp32 rescoring: one thread per candidate
    if (tid < NCAND) {
        if (tid < cnt) {
            int c = cidx[tid];
            const float* xr = g_xp + (size_t)p * CC;
            const float* xc = g_xp + (size_t)(bbase + c) * CC;
            float d = 0.f;
#pragma unroll
            for (int i = 0; i < 16; i++) {
                float4 a = *reinterpret_cast<const float4*>(xr + i * 4);
                float4 bq = *reinterpret_cast<const float4*>(xc + i * 4);
                d = fmaf(a.x, bq.x, d);
                d = fmaf(a.y, bq.y, d);
                d = fmaf(a.z, bq.z, d);
                d = fmaf(a.w, bq.w, d);
            }
            csc[tid] = fmaf(-2.f, d, g_sq[bbase + c]);
        } else {
            csc[tid] = 3.0e38f;
            cidx[tid] = 0x7fffffff;
        }
    }
    __syncthreads();

    // rank counting -> top-20
    if (tid < NCAND) {
        float s = csc[tid];
        int   ii = cidx[tid];
        int r = 0;
#pragma unroll
        for (int j = 0; j < NCAND; j++) {
            float sj = csc[j];
            int ij = cidx[j];
            r += (sj < s) || (sj == s && ij < ii);
        }
        if (r < KK) g_idx[(size_t)p * KK + r] = ii;
    }
}

// ===================== kernel C: u = W1 @ x, v = (W2-W1) @ x (8 outputs/thread) =====================
__global__ void __launch_bounds__(128) gemm_uv_kernel(const float* __restrict__ x,
                                                      const float* __restrict__ W) {
    int b = blockIdx.z, og = blockIdx.y;
    int n = blockIdx.x * 128 + threadIdx.x;

    __shared__ float W1s[8][64];
    __shared__ float Wds[8][64];
    for (int i = threadIdx.x; i < 8 * 64; i += 128) {
        int oo = i >> 6, c = i & 63;
        int o = og * 8 + oo;
        float w1 = W[o * 2 * CC + c];
        float w2 = W[o * 2 * CC + CC + c];
        W1s[oo][c] = w1;
        Wds[oo][c] = w2 - w1;
    }
    __syncthreads();

    float ua[8], va[8];
#pragma unroll
    for (int oo = 0; oo < 8; oo++) { ua[oo] = 0.f; va[oo] = 0.f; }

    const float* xb = x + (size_t)b * CC * NN + n;
#pragma unroll
    for (int ch = 0; ch < CC; ch++) {
        float xv = xb[(size_t)ch * NN];
#pragma unroll
        for (int oo = 0; oo < 8; oo++) {
            ua[oo] = fmaf(W1s[oo][ch], xv, ua[oo]);
            va[oo] = fmaf(Wds[oo][ch], xv, va[oo]);
        }
    }

    float* up = g_u + ((size_t)b * NN + n) * OUTC + og * 8;
    float* vp = g_v + ((size_t)b * NN + n) * OUTC + og * 8;
#pragma unroll
    for (int oo = 0; oo < 8; oo += 4) {
        *reinterpret_cast<float4*>(up + oo) = make_float4(ua[oo], ua[oo + 1], ua[oo + 2], ua[oo + 3]);
        *reinterpret_cast<float4*>(vp + oo) = make_float4(va[oo], va[oo + 1], va[oo + 2], va[oo + 3]);
    }
}

// ===================== kernel D: edges =====================
__global__ void __launch_bounds__(256) edge_kernel() {
    __shared__ float ssum[OUTC];
    __shared__ float ssq[OUTC];
    int tid = threadIdx.x, lane = tid & 31, wrp = tid >> 5;
    if (tid < OUTC) { ssum[tid] = 0.f; ssq[tid] = 0.f; }
    __syncthreads();

    int p0 = blockIdx.x * 64;
    float lsum0 = 0.f, lsq0 = 0.f, lsum1 = 0.f, lsq1 = 0.f;

    for (int i = 0; i < 8; i++) {
        int p = p0 + wrp * 8 + i;
        const float* vp = g_v + (size_t)p * OUTC;
        float v0 = vp[lane], v1 = vp[lane + 32];
        int idxv = 0;
        if (lane < KK) idxv = g_idx[(size_t)p * KK + lane];
        int bbase = (p >> 12) << 12;

        float mx0 = -3.0e38f, mn0 = 3.0e38f, mx1 = -3.0e38f, mn1 = 3.0e38f;
#pragma unroll
        for (int k = 0; k < KK; k++) {
            int j = __shfl_sync(0xffffffffu, idxv, k);
            const float* uj = g_u + (size_t)(bbase + j) * OUTC;
            float z0 = uj[lane] + v0;
            float z1 = uj[lane + 32] + v1;
            mx0 = fmaxf(mx0, z0); mn0 = fminf(mn0, z0);
            mx1 = fmaxf(mx1, z1); mn1 = fminf(mn1, z1);
            lsum0 += z0; lsq0 = fmaf(z0, z0, lsq0);
            lsum1 += z1; lsq1 = fmaf(z1, z1, lsq1);
        }
        float* mxp = g_mx + (size_t)p * OUTC;
        float* mnp = g_mn + (size_t)p * OUTC;
        mxp[lane] = mx0; mxp[lane + 32] = mx1;
        mnp[lane] = mn0; mnp[lane + 32] = mn1;
    }

    atomicAdd(&ssum[lane], lsum0);
    atomicAdd(&ssum[lane + 32], lsum1);
    atomicAdd(&ssq[lane], lsq0);
    atomicAdd(&ssq[lane + 32], lsq1);
    __syncthreads();
    if (tid < OUTC) {
        atomicAdd(&g_sum[tid], ssum[tid]);
        atomicAdd(&g_sumsq[tid], ssq[tid]);
    }
}

// ===================== kernel E0: finalize BN affine =====================
__global__ void stats_kernel(const float* __restrict__ gamma, const float* __restrict__ beta) {
    int o = threadIdx.x;
    const float cnt = (float)((size_t)BB * NN * KK);
    float mean = g_sum[o] / cnt;
    float var = g_sumsq[o] / cnt - mean * mean;
    float s = gamma[o] * rsqrtf(var + 1e-5f);
    g_s[o] = s;
    g_t[o] = fmaf(-mean, s, beta[o]);
}

// ===================== kernel E: BN + LeakyReLU + transpose =====================
__global__ void __launch_bounds__(256) out_kernel(float* __restrict__ out) {
    __shared__ float tile[64][65];
    __shared__ float ss[OUTC], tt[OUTC];
    int tid = threadIdx.x;
    if (tid < OUTC) { ss[tid] = g_s[tid]; tt[tid] = g_t[tid]; }
    __syncthreads();

    int p0 = blockIdx.x * 64;
    int b = p0 >> 12;
    int n0 = p0 & (NN - 1);

#pragma unroll
    for (int j = 0; j < 16; j++) {
        int i = tid + j * 256;
        int nn = i >> 6, o = i & 63;
        size_t base = (size_t)(p0 + nn) * OUTC + o;
        float s = ss[o];
        float z = (s >= 0.f) ? g_mx[base] : g_mn[base];
        float y = fmaf(s, z, tt[o]);
        y = (y >= 0.f) ? y : 0.2f * y;
        tile[o][nn] = y;
    }
    __syncthreads();
#pragma unroll
    for (int j = 0; j < 16; j++) {
        int i = tid + j * 256;
        int o = i >> 6, nn = i & 63;
        out[((size_t)(b * OUTC + o)) * NN + n0 + nn] = tile[o][nn];
    }
}

// ===================== launch =====================
extern "C" void kernel_launch(void* const* d_in, const int* in_sizes, int n_in,
                              void* d_out, int out_size) {
    const float* x     = (const float*)d_in[0];
    const float* W     = (const float*)d_in[1];
    const float* gamma = (const float*)d_in[2];
    const float* beta  = (const float*)d_in[3];
    float* out = (float*)d_out;

    static cudaStream_t s2 = nullptr;
    static cudaEvent_t evA = nullptr, evB = nullptr;
    if (s2 == nullptr) {
        cudaStreamCreateWithFlags(&s2, cudaStreamNonBlocking);
        cudaEventCreateWithFlags(&evA, cudaEventDisableTiming);
        cudaEventCreateWithFlags(&evB, cudaEventDisableTiming);
        cudaFuncSetAttribute(knn_gemm_kernel, cudaFuncAttributeMaxDynamicSharedMemorySize, SM_TOTAL);
    }

    // fork: uv depends only on input x — run concurrently with prep/knn/select
    cudaEventRecord(evA, 0);
    cudaStreamWaitEvent(s2, evA, 0);
    gemm_uv_kernel<<<dim3(NN / 128, 8, BB), 128, 0, s2>>>(x, W);
    cudaEventRecord(evB, s2);

    prep_kernel<<<(BB * NN) / 128, 128>>>(x);
    knn_gemm_kernel<<<NCTA, 256, SM_TOTAL>>>();
    select_rerank_kernel<<<BB * NN, 128>>>();

    cudaStreamWaitEvent(0, evB, 0);
    edge_kernel<<<(BB * NN) / 64, 256>>>();
    stats_kernel<<<1, OUTC>>>(gamma, beta);
    out_kernel<<<(BB * NN) / 64, 256>>>(out);
}